// round 6
// baseline (speedup 1.0000x reference)
#include <cuda_runtime.h>
#include <cstdint>
#include <cstddef>

// Problem constants
#define B_   4
#define T_   2048
#define DM_  512
#define H_   8
#define DH_  64
#define BH_  (B_ * H_)     // 32
#define M_   (B_ * T_)     // 8192

// Scratch (device globals; no allocations allowed)
__device__ float g_q  [(size_t)BH_ * T_ * DH_];  // (b,h,t,d)
__device__ float g_kT [(size_t)BH_ * DH_ * T_];  // (b,h,d,t)  K pre-transposed
__device__ float g_v  [(size_t)BH_ * T_ * DH_];  // (b,h,t,d)
__device__ float g_ctx[(size_t)M_ * DM_];        // (b*T+t, h*64+d) row-major

// ---------------------------------------------------------------------------
// Projection GEMM: out[m,n] = sum_k X[m,k] * W[n,k] + bias[n]
// M=8192, N=512, K=512.  Block tile 64x64, BK=16, 256 threads, 4x4 micro-tile.
// mode 0: scatter to (b,h,t,d); mode 1: scatter to (b,h,d,t); mode 2: row-major
// ---------------------------------------------------------------------------
__global__ __launch_bounds__(256) void gemm_proj(
    const float* __restrict__ X, const float* __restrict__ W,
    const float* __restrict__ bias, float* __restrict__ out, int mode)
{
    __shared__ float sA[16][68];
    __shared__ float sB[16][68];

    const int tid = threadIdx.x;
    const int tx = tid & 15;
    const int ty = tid >> 4;
    const int m0 = blockIdx.y * 64;
    const int n0 = blockIdx.x * 64;

    const int lr = tid >> 2;
    const int lc = (tid & 3) * 4;

    float acc[4][4] = {};

    for (int k0 = 0; k0 < 512; k0 += 16) {
        float4 av = *(const float4*)&X[(size_t)(m0 + lr) * 512 + k0 + lc];
        float4 bv = *(const float4*)&W[(size_t)(n0 + lr) * 512 + k0 + lc];
        sA[lc + 0][lr] = av.x; sA[lc + 1][lr] = av.y;
        sA[lc + 2][lr] = av.z; sA[lc + 3][lr] = av.w;
        sB[lc + 0][lr] = bv.x; sB[lc + 1][lr] = bv.y;
        sB[lc + 2][lr] = bv.z; sB[lc + 3][lr] = bv.w;
        __syncthreads();

        #pragma unroll
        for (int kk = 0; kk < 16; kk++) {
            float4 a = *(const float4*)&sA[kk][ty * 4];
            float4 b = *(const float4*)&sB[kk][tx * 4];
            acc[0][0] += a.x * b.x; acc[0][1] += a.x * b.y;
            acc[0][2] += a.x * b.z; acc[0][3] += a.x * b.w;
            acc[1][0] += a.y * b.x; acc[1][1] += a.y * b.y;
            acc[1][2] += a.y * b.z; acc[1][3] += a.y * b.w;
            acc[2][0] += a.z * b.x; acc[2][1] += a.z * b.y;
            acc[2][2] += a.z * b.z; acc[2][3] += a.z * b.w;
            acc[3][0] += a.w * b.x; acc[3][1] += a.w * b.y;
            acc[3][2] += a.w * b.z; acc[3][3] += a.w * b.w;
        }
        __syncthreads();
    }

    #pragma unroll
    for (int i = 0; i < 4; i++) {
        const int m = m0 + ty * 4 + i;
        const int bb = m >> 11;
        const int t  = m & 2047;
        #pragma unroll
        for (int j = 0; j < 4; j++) {
            const int n = n0 + tx * 4 + j;
            const float v = acc[i][j] + bias[n];
            size_t o;
            if (mode == 0)      o = (((size_t)bb * H_ + (n >> 6)) * T_ + t) * DH_ + (n & 63);
            else if (mode == 1) o = (((size_t)bb * H_ + (n >> 6)) * DH_ + (n & 63)) * T_ + t;
            else                o = (size_t)m * DM_ + n;
            out[o] = v;
        }
    }
}

// ---------------------------------------------------------------------------
// Fused attention per (bh, 16-row q-block). 512 threads.
// Phase 1: S = (Q/8) @ K^T  into sS[16][2048] with 4x4 register micro-tiles
//          (rg=tid>>7 row-group, cg=tid&127 col-group), K chunks [16][512]
//          double-buffered -> FMA-bound instead of smem-crossbar-bound.
// Phase 2: warp-per-row softmax over sS; normalized probs -> gattn.
// Phase 3: ctx = P @ V, 8-way t-split (ts,rg,cg), V chunks [128][64] double-
//          buffered, partials reduced through smem.
// smem: sS 128KB + sQT 4KB + sK 2x32KB = 196KB  (1 CTA/SM)
// ---------------------------------------------------------------------------
#define QB_ 16

__global__ __launch_bounds__(512) void attn_kernel(
    const float* __restrict__ gq, const float* __restrict__ gkT,
    const float* __restrict__ gv, float* __restrict__ gctx,
    float* __restrict__ gattn)
{
    extern __shared__ float sm[];
    float* sS  = sm;                        // [16][2048]
    float* sQT = sm + QB_ * T_;             // [64][16]  Q transposed, scaled
    float* sK  = sQT + DH_ * QB_;           // 2 x 8192

    const int tid = threadIdx.x;
    const int qb = blockIdx.x;              // 0..127
    const int bh = blockIdx.y;              // 0..31
    const int qrow0 = qb * QB_;

    const float* kbase = gkT + (size_t)bh * DH_ * T_;
    const float* vbase = gv  + (size_t)bh * T_ * DH_;

    // --- load Q^T (scaled by 1/sqrt(64)=0.125): sQT[d][r] ---
    {
        const int r = tid >> 5, d = (tid & 31) * 2;
        float2 v = *(const float2*)&gq[((size_t)bh * T_ + qrow0 + r) * DH_ + d];
        sQT[d * QB_ + r]       = v.x * 0.125f;
        sQT[(d + 1) * QB_ + r] = v.y * 0.125f;
    }

    // ============ Phase 1: scores ============
    {
        const int rg = tid >> 7;        // 0..3
        const int cg = tid & 127;       // 0..127

        #pragma unroll
        for (int u = 0; u < 4; u++) {
            const int idx = u * 512 + tid;
            const int i = idx >> 7, c4 = idx & 127;
            *(float4*)&sK[(size_t)i * 512 + c4 * 4] =
                *(const float4*)&kbase[(size_t)i * T_ + c4 * 4];
        }
        __syncthreads();

        float4 acc0 = {0,0,0,0}, acc1 = {0,0,0,0}, acc2 = {0,0,0,0}, acc3 = {0,0,0,0};

        for (int cc = 0; cc < 16; cc++) {           // cc = st*4 + ch
            float4 pre[4];
            if (cc < 15) {
                const int nst = (cc + 1) >> 2, nch = (cc + 1) & 3;
                #pragma unroll
                for (int u = 0; u < 4; u++) {
                    const int idx = u * 512 + tid;
                    const int i = idx >> 7, c4 = idx & 127;
                    pre[u] = *(const float4*)&kbase[(size_t)(nch * 16 + i) * T_ + nst * 512 + c4 * 4];
                }
            }

            const float* kb = sK + (cc & 1) * 8192;
            const int ch = cc & 3;
            #pragma unroll
            for (int k = 0; k < 16; k++) {
                const int kka = ch * 16 + k;
                float4 qv = *(const float4*)&sQT[kka * QB_ + rg * 4];
                float4 kv = *(const float4*)&kb[k * 512 + cg * 4];
                acc0.x += qv.x * kv.x; acc0.y += qv.x * kv.y; acc0.z += qv.x * kv.z; acc0.w += qv.x * kv.w;
                acc1.x += qv.y * kv.x; acc1.y += qv.y * kv.y; acc1.z += qv.y * kv.z; acc1.w += qv.y * kv.w;
                acc2.x += qv.z * kv.x; acc2.y += qv.z * kv.y; acc2.z += qv.z * kv.z; acc2.w += qv.z * kv.w;
                acc3.x += qv.w * kv.x; acc3.y += qv.w * kv.y; acc3.z += qv.w * kv.z; acc3.w += qv.w * kv.w;
            }

            if (ch == 3) {
                const int st = cc >> 2;
                float* dst = sS + (size_t)(rg * 4) * T_ + st * 512 + cg * 4;
                *(float4*)&dst[0]      = acc0;
                *(float4*)&dst[T_]     = acc1;
                *(float4*)&dst[2 * T_] = acc2;
                *(float4*)&dst[3 * T_] = acc3;
                acc0 = acc1 = acc2 = acc3 = make_float4(0.f, 0.f, 0.f, 0.f);
            }
            __syncthreads();
            if (cc < 15) {
                float* dstb = sK + ((cc + 1) & 1) * 8192;
                #pragma unroll
                for (int u = 0; u < 4; u++) {
                    const int idx = u * 512 + tid;
                    const int i = idx >> 7, c4 = idx & 127;
                    *(float4*)&dstb[(size_t)i * 512 + c4 * 4] = pre[u];
                }
                __syncthreads();
            }
        }
    }

    // ============ Phase 2: softmax + attn write ============
    {
        const int w = tid >> 5, l = tid & 31;
        float* row = sS + (size_t)w * T_;
        float mx = -1e30f;
        for (int i = l; i < T_; i += 32) mx = fmaxf(mx, row[i]);
        #pragma unroll
        for (int o = 16; o > 0; o >>= 1) mx = fmaxf(mx, __shfl_xor_sync(0xffffffffu, mx, o));
        float sum = 0.f;
        for (int i = l; i < T_; i += 32) {
            float e = __expf(row[i] - mx);
            row[i] = e; sum += e;
        }
        #pragma unroll
        for (int o = 16; o > 0; o >>= 1) sum += __shfl_xor_sync(0xffffffffu, sum, o);
        const float inv = 1.f / sum;
        float4* rv = (float4*)row;
        float4* ga = (float4*)(gattn + ((size_t)bh * T_ + qrow0 + w) * T_);
        for (int i = l; i < T_ / 4; i += 32) {
            float4 p = rv[i];
            p.x *= inv; p.y *= inv; p.z *= inv; p.w *= inv;
            rv[i] = p; ga[i] = p;
        }
    }
    __syncthreads();

    // ============ Phase 3: ctx = P @ V ============
    {
        const int ts = tid >> 6;          // 0..7
        const int rg = (tid >> 4) & 3;    // 0..3
        const int cg = tid & 15;          // 0..15

        #pragma unroll
        for (int u = 0; u < 4; u++) {
            const int idx = u * 512 + tid;
            const int j = idx >> 4, d4 = idx & 15;
            *(float4*)&sK[(size_t)j * 64 + d4 * 4] =
                *(const float4*)&vbase[(size_t)j * DH_ + d4 * 4];
        }
        __syncthreads();

        float4 f0 = {0,0,0,0}, f1 = {0,0,0,0}, f2 = {0,0,0,0}, f3 = {0,0,0,0};

        for (int c = 0; c < 16; c++) {
            float4 pre[4];
            if (c < 15) {
                #pragma unroll
                for (int u = 0; u < 4; u++) {
                    const int idx = u * 512 + tid;
                    const int j = idx >> 4, d4 = idx & 15;
                    pre[u] = *(const float4*)&vbase[(size_t)((c + 1) * 128 + j) * DH_ + d4 * 4];
                }
            }

            const float* vb = sK + (c & 1) * 8192;
            #pragma unroll
            for (int it = 0; it < 16; it++) {
                const int jj = ts + it * 8;
                const float* srow = sS + (size_t)(rg * 4) * T_ + c * 128 + jj;
                float p0 = srow[0];
                float p1 = srow[T_];
                float p2 = srow[2 * T_];
                float p3 = srow[3 * T_];
                float4 vv = *(const float4*)&vb[jj * 64 + cg * 4];
                f0.x += p0 * vv.x; f0.y += p0 * vv.y; f0.z += p0 * vv.z; f0.w += p0 * vv.w;
                f1.x += p1 * vv.x; f1.y += p1 * vv.y; f1.z += p1 * vv.z; f1.w += p1 * vv.w;
                f2.x += p2 * vv.x; f2.y += p2 * vv.y; f2.z += p2 * vv.z; f2.w += p2 * vv.w;
                f3.x += p3 * vv.x; f3.y += p3 * vv.y; f3.z += p3 * vv.z; f3.w += p3 * vv.w;
            }
            __syncthreads();
            if (c < 15) {
                float* dstb = sK + ((c + 1) & 1) * 8192;
                #pragma unroll
                for (int u = 0; u < 4; u++) {
                    const int idx = u * 512 + tid;
                    const int j = idx >> 4, d4 = idx & 15;
                    *(float4*)&dstb[(size_t)j * 64 + d4 * 4] = pre[u];
                }
                __syncthreads();
            }
        }

        // reduce the 8 t-slices through smem (reuse sK region)
        float* sRed = sK;   // [8][16][64]
        {
            float* base = sRed + (size_t)ts * 1024 + (size_t)(rg * 4) * 64 + cg * 4;
            *(float4*)&base[0]   = f0;
            *(float4*)&base[64]  = f1;
            *(float4*)&base[128] = f2;
            *(float4*)&base[192] = f3;
        }
        __syncthreads();

        const int row = tid >> 5, d2 = (tid & 31) * 2;
        float2 s = {0.f, 0.f};
        #pragma unroll
        for (int t = 0; t < 8; t++) {
            float2 v = *(const float2*)&sRed[(size_t)t * 1024 + row * 64 + d2];
            s.x += v.x; s.y += v.y;
        }
        const int bb = bh >> 3, hh = bh & 7;
        const int m = bb * T_ + qrow0 + row;
        *(float2*)&gctx[(size_t)m * DM_ + hh * DH_ + d2] = s;
    }
}

// ---------------------------------------------------------------------------

extern "C" void kernel_launch(void* const* d_in, const int* in_sizes, int n_in,
                              void* d_out, int out_size)
{
    const float* Q  = (const float*)d_in[0];
    const float* K  = (const float*)d_in[1];
    const float* V  = (const float*)d_in[2];
    const float* Wq = (const float*)d_in[3];
    const float* bq = (const float*)d_in[4];
    const float* Wk = (const float*)d_in[5];
    const float* bk = (const float*)d_in[6];
    const float* Wv = (const float*)d_in[7];
    const float* bv = (const float*)d_in[8];
    const float* Wo = (const float*)d_in[9];
    const float* bo = (const float*)d_in[10];

    float* out  = (float*)d_out;
    float* attn = out + (size_t)M_ * DM_;   // tuple order: (out, attn)

    float *pq, *pkT, *pv, *pctx;
    cudaGetSymbolAddress((void**)&pq,   g_q);
    cudaGetSymbolAddress((void**)&pkT,  g_kT);
    cudaGetSymbolAddress((void**)&pv,   g_v);
    cudaGetSymbolAddress((void**)&pctx, g_ctx);

    const int smem_bytes = (QB_ * T_ + DH_ * QB_ + 2 * 8192) * (int)sizeof(float); // 200704
    cudaFuncSetAttribute(attn_kernel, cudaFuncAttributeMaxDynamicSharedMemorySize, smem_bytes);

    dim3 ggrid(DM_ / 64, M_ / 64);   // (8, 128)

    gemm_proj<<<ggrid, 256>>>(Q, Wq, bq, pq,  0);
    gemm_proj<<<ggrid, 256>>>(K, Wk, bk, pkT, 1);
    gemm_proj<<<ggrid, 256>>>(V, Wv, bv, pv,  0);

    attn_kernel<<<dim3(T_ / QB_, BH_), 512, smem_bytes>>>(pq, pkT, pv, pctx, attn);

    gemm_proj<<<ggrid, 256>>>(pctx, Wo, bo, out, 2);
}

// round 12
// speedup vs baseline: 1.9518x; 1.9518x over previous
#include <cuda_runtime.h>
#include <cuda_bf16.h>
#include <mma.h>
#include <cstdint>
#include <cstddef>

using namespace nvcuda;

// Problem constants
#define B_   4
#define T_   2048
#define DM_  512
#define H_   8
#define DH_  64
#define BH_  (B_ * H_)     // 32
#define M_   (B_ * T_)     // 8192

// Scratch (device globals; no allocations allowed)
__device__ float g_q  [(size_t)BH_ * T_ * DH_];  // (b,h,t,d)
__device__ float g_k  [(size_t)BH_ * T_ * DH_];  // (b,h,t,d)
__device__ float g_v  [(size_t)BH_ * T_ * DH_];  // (b,h,t,d)
__device__ float g_ctx[(size_t)M_ * DM_];        // (b*T+t, h*64+d)

// fp32 -> bf16 hi + bf16 lo split (hi+lo reproduces fp32 to ~2^-17 rel)
__device__ __forceinline__ void split4(float4 v, uint2& hi, uint2& lo) {
    __nv_bfloat16 h0 = __float2bfloat16(v.x), h1 = __float2bfloat16(v.y);
    __nv_bfloat16 h2 = __float2bfloat16(v.z), h3 = __float2bfloat16(v.w);
    __nv_bfloat16 l0 = __float2bfloat16(v.x - __bfloat162float(h0));
    __nv_bfloat16 l1 = __float2bfloat16(v.y - __bfloat162float(h1));
    __nv_bfloat16 l2 = __float2bfloat16(v.z - __bfloat162float(h2));
    __nv_bfloat16 l3 = __float2bfloat16(v.w - __bfloat162float(h3));
    uint16_t uh0 = *(uint16_t*)&h0, uh1 = *(uint16_t*)&h1;
    uint16_t uh2 = *(uint16_t*)&h2, uh3 = *(uint16_t*)&h3;
    uint16_t ul0 = *(uint16_t*)&l0, ul1 = *(uint16_t*)&l1;
    uint16_t ul2 = *(uint16_t*)&l2, ul3 = *(uint16_t*)&l3;
    hi.x = (uint32_t)uh0 | ((uint32_t)uh1 << 16);
    hi.y = (uint32_t)uh2 | ((uint32_t)uh3 << 16);
    lo.x = (uint32_t)ul0 | ((uint32_t)ul1 << 16);
    lo.y = (uint32_t)ul2 | ((uint32_t)ul3 << 16);
}

typedef wmma::fragment<wmma::matrix_a, 16, 16, 16, __nv_bfloat16, wmma::row_major> FragA;
typedef wmma::fragment<wmma::matrix_b, 16, 16, 16, __nv_bfloat16, wmma::col_major> FragBc;
typedef wmma::fragment<wmma::matrix_b, 16, 16, 16, __nv_bfloat16, wmma::row_major> FragBr;
typedef wmma::fragment<wmma::accumulator, 16, 16, 16, float> FragC;

// ---------------------------------------------------------------------------
// Projection GEMM (wmma split-bf16): out[m,n] = sum_k X[m,k]*W[n,k] + bias[n]
// CTA tile 128(M) x 64(N), BK=32, 16 k-chunks, 256 threads = 8 warps (4m x 2n),
// warp tile 32x32 (2x2 wmma frags), 3 MMAs (AhBh, AhBl, AlBh) per tile pair.
// mode 0: scatter to (b,h,t,d); mode 2: row-major m*512+n
// ---------------------------------------------------------------------------
__global__ __launch_bounds__(256) void gemm_proj(
    const float* __restrict__ X, const float* __restrict__ W,
    const float* __restrict__ bias, float* __restrict__ out, int mode)
{
    __shared__ __align__(16) char sbuf[36864];
    __nv_bfloat16* Ah = (__nv_bfloat16*)sbuf;      // [128][40]
    __nv_bfloat16* Al = Ah + 5120;
    __nv_bfloat16* Bh = Ah + 10240;                // [64][40]
    __nv_bfloat16* Bl = Ah + 12800;
    float* Cs = (float*)sbuf;                      // [128][72] (epilogue reuse)

    const int tid = threadIdx.x;
    const int wid = tid >> 5;
    const int m0 = blockIdx.y * 128;
    const int n0 = blockIdx.x * 64;
    const int wm0 = (wid >> 1) * 32;
    const int wn0 = (wid & 1) * 32;

    FragC acc[2][2];
    #pragma unroll
    for (int i = 0; i < 2; i++)
        #pragma unroll
        for (int j = 0; j < 2; j++) wmma::fill_fragment(acc[i][j], 0.f);

    float4 px[4], pw[2];

    // load chunk 0 directly
    #pragma unroll
    for (int u = 0; u < 4; u++) {
        const int idx = u * 256 + tid, r = idx >> 3, c = idx & 7;
        px[u] = *(const float4*)&X[(size_t)(m0 + r) * 512 + c * 4];
    }
    #pragma unroll
    for (int u = 0; u < 2; u++) {
        const int idx = u * 256 + tid, r = idx >> 3, c = idx & 7;
        pw[u] = *(const float4*)&W[(size_t)(n0 + r) * 512 + c * 4];
    }
    #pragma unroll
    for (int u = 0; u < 4; u++) {
        const int idx = u * 256 + tid, r = idx >> 3, c = idx & 7;
        uint2 hi, lo; split4(px[u], hi, lo);
        *(uint2*)&Ah[r * 40 + c * 4] = hi;
        *(uint2*)&Al[r * 40 + c * 4] = lo;
    }
    #pragma unroll
    for (int u = 0; u < 2; u++) {
        const int idx = u * 256 + tid, r = idx >> 3, c = idx & 7;
        uint2 hi, lo; split4(pw[u], hi, lo);
        *(uint2*)&Bh[r * 40 + c * 4] = hi;
        *(uint2*)&Bl[r * 40 + c * 4] = lo;
    }
    __syncthreads();

    for (int c0 = 0; c0 < 16; c0++) {
        if (c0 < 15) {
            const int k0 = (c0 + 1) * 32;
            #pragma unroll
            for (int u = 0; u < 4; u++) {
                const int idx = u * 256 + tid, r = idx >> 3, c = idx & 7;
                px[u] = *(const float4*)&X[(size_t)(m0 + r) * 512 + k0 + c * 4];
            }
            #pragma unroll
            for (int u = 0; u < 2; u++) {
                const int idx = u * 256 + tid, r = idx >> 3, c = idx & 7;
                pw[u] = *(const float4*)&W[(size_t)(n0 + r) * 512 + k0 + c * 4];
            }
        }

        #pragma unroll
        for (int ks = 0; ks < 32; ks += 16) {
            FragA ah[2], al[2];
            FragBc bh[2], bl[2];
            #pragma unroll
            for (int i = 0; i < 2; i++) {
                wmma::load_matrix_sync(ah[i], &Ah[(wm0 + i * 16) * 40 + ks], 40);
                wmma::load_matrix_sync(al[i], &Al[(wm0 + i * 16) * 40 + ks], 40);
            }
            #pragma unroll
            for (int j = 0; j < 2; j++) {
                wmma::load_matrix_sync(bh[j], &Bh[(wn0 + j * 16) * 40 + ks], 40);
                wmma::load_matrix_sync(bl[j], &Bl[(wn0 + j * 16) * 40 + ks], 40);
            }
            #pragma unroll
            for (int i = 0; i < 2; i++)
                #pragma unroll
                for (int j = 0; j < 2; j++) {
                    wmma::mma_sync(acc[i][j], ah[i], bh[j], acc[i][j]);
                    wmma::mma_sync(acc[i][j], ah[i], bl[j], acc[i][j]);
                    wmma::mma_sync(acc[i][j], al[i], bh[j], acc[i][j]);
                }
        }
        __syncthreads();
        if (c0 < 15) {
            #pragma unroll
            for (int u = 0; u < 4; u++) {
                const int idx = u * 256 + tid, r = idx >> 3, c = idx & 7;
                uint2 hi, lo; split4(px[u], hi, lo);
                *(uint2*)&Ah[r * 40 + c * 4] = hi;
                *(uint2*)&Al[r * 40 + c * 4] = lo;
            }
            #pragma unroll
            for (int u = 0; u < 2; u++) {
                const int idx = u * 256 + tid, r = idx >> 3, c = idx & 7;
                uint2 hi, lo; split4(pw[u], hi, lo);
                *(uint2*)&Bh[r * 40 + c * 4] = hi;
                *(uint2*)&Bl[r * 40 + c * 4] = lo;
            }
            __syncthreads();
        }
    }

    // epilogue: frags -> smem -> bias add -> scatter
    #pragma unroll
    for (int i = 0; i < 2; i++)
        #pragma unroll
        for (int j = 0; j < 2; j++)
            wmma::store_matrix_sync(&Cs[(wm0 + i * 16) * 72 + wn0 + j * 16],
                                    acc[i][j], 72, wmma::mem_row_major);
    __syncthreads();

    #pragma unroll
    for (int u = 0; u < 8; u++) {
        const int idx = u * 256 + tid;
        const int row = idx >> 4, c4 = idx & 15;
        float4 v = *(const float4*)&Cs[row * 72 + c4 * 4];
        float4 bv = *(const float4*)&bias[n0 + c4 * 4];
        v.x += bv.x; v.y += bv.y; v.z += bv.z; v.w += bv.w;
        const int m = m0 + row;
        size_t o;
        if (mode == 0) {
            const int bb = m >> 11, t = m & 2047, head = n0 >> 6;
            o = (((size_t)bb * H_ + head) * T_ + t) * DH_ + c4 * 4;
        } else {
            o = (size_t)m * DM_ + n0 + c4 * 4;
        }
        *(float4*)&out[o] = v;
    }
}

// ---------------------------------------------------------------------------
// QK kernel: raw scores S[128q][128t] per CTA, K-dim = 64 in one shot.
// 8 warps (4m x 2n), warp tile 32q x 64t (2x4 frags). Direct fp32 store.
// dynamic smem: Qhi/Qlo/Khi/Klo each [128][72] bf16 = 73728 B
// ---------------------------------------------------------------------------
#define QK_SMEM 73728

__global__ __launch_bounds__(256) void qk_kernel(
    const float* __restrict__ gq, const float* __restrict__ gk,
    float* __restrict__ graw)
{
    extern __shared__ __align__(16) char dsm[];
    __nv_bfloat16* Qh = (__nv_bfloat16*)dsm;   // [128][72]
    __nv_bfloat16* Ql = Qh + 9216;
    __nv_bfloat16* Kh = Qh + 18432;
    __nv_bfloat16* Kl = Qh + 27648;

    const int tid = threadIdx.x;
    const int wid = tid >> 5;
    const int t0 = blockIdx.x * 128;
    const int q0 = blockIdx.y * 128;
    const int bh = blockIdx.z;

    #pragma unroll
    for (int u = 0; u < 8; u++) {
        const int idx = u * 256 + tid, r = idx >> 4, c = idx & 15;
        float4 v = *(const float4*)&gq[((size_t)bh * T_ + q0 + r) * DH_ + c * 4];
        v.x *= 0.125f; v.y *= 0.125f; v.z *= 0.125f; v.w *= 0.125f;
        uint2 hi, lo; split4(v, hi, lo);
        *(uint2*)&Qh[r * 72 + c * 4] = hi;
        *(uint2*)&Ql[r * 72 + c * 4] = lo;
        float4 w = *(const float4*)&gk[((size_t)bh * T_ + t0 + r) * DH_ + c * 4];
        split4(w, hi, lo);
        *(uint2*)&Kh[r * 72 + c * 4] = hi;
        *(uint2*)&Kl[r * 72 + c * 4] = lo;
    }
    __syncthreads();

    const int wm0 = (wid >> 1) * 32;
    const int wn0 = (wid & 1) * 64;

    FragC acc[2][4];
    #pragma unroll
    for (int i = 0; i < 2; i++)
        #pragma unroll
        for (int j = 0; j < 4; j++) wmma::fill_fragment(acc[i][j], 0.f);

    #pragma unroll
    for (int ks = 0; ks < 64; ks += 16) {
        FragA ah[2], al[2];
        #pragma unroll
        for (int i = 0; i < 2; i++) {
            wmma::load_matrix_sync(ah[i], &Qh[(wm0 + i * 16) * 72 + ks], 72);
            wmma::load_matrix_sync(al[i], &Ql[(wm0 + i * 16) * 72 + ks], 72);
        }
        #pragma unroll
        for (int j = 0; j < 4; j++) {
            FragBc bh, bl;
            wmma::load_matrix_sync(bh, &Kh[(wn0 + j * 16) * 72 + ks], 72);
            wmma::load_matrix_sync(bl, &Kl[(wn0 + j * 16) * 72 + ks], 72);
            #pragma unroll
            for (int i = 0; i < 2; i++) {
                wmma::mma_sync(acc[i][j], ah[i], bh, acc[i][j]);
                wmma::mma_sync(acc[i][j], ah[i], bl, acc[i][j]);
                wmma::mma_sync(acc[i][j], al[i], bh, acc[i][j]);
            }
        }
    }

    #pragma unroll
    for (int i = 0; i < 2; i++)
        #pragma unroll
        for (int j = 0; j < 4; j++)
            wmma::store_matrix_sync(
                graw + ((size_t)bh * T_ + q0 + wm0 + i * 16) * T_ + t0 + wn0 + j * 16,
                acc[i][j], T_, wmma::mem_row_major);
}

// ---------------------------------------------------------------------------
// Row softmax in-place: one 256-thread block per row of 2048.
// ---------------------------------------------------------------------------
__global__ __launch_bounds__(256) void softmax_kernel(float* __restrict__ a)
{
    __shared__ float red[8];
    const size_t r = blockIdx.x;
    float4* row = (float4*)(a + r * T_);
    const int tid = threadIdx.x, l = tid & 31, w = tid >> 5;

    float4 v0 = row[tid], v1 = row[tid + 256];
    float mx = fmaxf(fmaxf(fmaxf(v0.x, v0.y), fmaxf(v0.z, v0.w)),
                     fmaxf(fmaxf(v1.x, v1.y), fmaxf(v1.z, v1.w)));
    #pragma unroll
    for (int o = 16; o > 0; o >>= 1) mx = fmaxf(mx, __shfl_xor_sync(0xffffffffu, mx, o));
    if (l == 0) red[w] = mx;
    __syncthreads();
    float m = red[0];
    #pragma unroll
    for (int i = 1; i < 8; i++) m = fmaxf(m, red[i]);
    __syncthreads();

    v0.x = __expf(v0.x - m); v0.y = __expf(v0.y - m);
    v0.z = __expf(v0.z - m); v0.w = __expf(v0.w - m);
    v1.x = __expf(v1.x - m); v1.y = __expf(v1.y - m);
    v1.z = __expf(v1.z - m); v1.w = __expf(v1.w - m);
    float s = v0.x + v0.y + v0.z + v0.w + v1.x + v1.y + v1.z + v1.w;
    #pragma unroll
    for (int o = 16; o > 0; o >>= 1) s += __shfl_xor_sync(0xffffffffu, s, o);
    if (l == 0) red[w] = s;
    __syncthreads();
    float sum = 0.f;
    #pragma unroll
    for (int i = 0; i < 8; i++) sum += red[i];
    const float inv = 1.f / sum;

    v0.x *= inv; v0.y *= inv; v0.z *= inv; v0.w *= inv;
    v1.x *= inv; v1.y *= inv; v1.z *= inv; v1.w *= inv;
    row[tid] = v0; row[tid + 256] = v1;
}

// ---------------------------------------------------------------------------
// PV kernel: ctx[128q][64d] = P[128][2048] @ V[2048][64] per (bh, qb).
// BK=32, 64 chunks, reg prefetch. 8 warps (4m x 2n), warp 32x32 (2x2 frags).
// V consumed row_major (natural (t,d) layout). smem 29696 B static.
// ---------------------------------------------------------------------------
__global__ __launch_bounds__(256) void pv_kernel(
    const float* __restrict__ gp, const float* __restrict__ gv,
    float* __restrict__ gctx)
{
    __shared__ __align__(16) char sbuf[29696];
    __nv_bfloat16* Ph = (__nv_bfloat16*)sbuf;      // [128][40]
    __nv_bfloat16* Pl = Ph + 5120;
    __nv_bfloat16* Vh = Ph + 10240;                // [32][72]
    __nv_bfloat16* Vl = Ph + 12544;

    const int tid = threadIdx.x;
    const int wid = tid >> 5;
    const int q0 = blockIdx.x * 128;
    const int bh = blockIdx.y;
    const int wm0 = (wid >> 1) * 32;
    const int wn0 = (wid & 1) * 32;

    FragC acc[2][2];
    #pragma unroll
    for (int i = 0; i < 2; i++)
        #pragma unroll
        for (int j = 0; j < 2; j++) wmma::fill_fragment(acc[i][j], 0.f);

    float4 pp[4], vv[2];

    // chunk 0 direct
    #pragma unroll
    for (int u = 0; u < 4; u++) {
        const int idx = u * 256 + tid, r = idx >> 3, c = idx & 7;
        pp[u] = *(const float4*)&gp[((size_t)bh * T_ + q0 + r) * T_ + c * 4];
    }
    #pragma unroll
    for (int u = 0; u < 2; u++) {
        const int idx = u * 256 + tid, r = idx >> 4, c = idx & 15;
        vv[u] = *(const float4*)&gv[((size_t)bh * T_ + r) * DH_ + c * 4];
    }
    #pragma unroll
    for (int u = 0; u < 4; u++) {
        const int idx = u * 256 + tid, r = idx >> 3, c = idx & 7;
        uint2 hi, lo; split4(pp[u], hi, lo);
        *(uint2*)&Ph[r * 40 + c * 4] = hi;
        *(uint2*)&Pl[r * 40 + c * 4] = lo;
    }
    #pragma unroll
    for (int u = 0; u < 2; u++) {
        const int idx = u * 256 + tid, r = idx >> 4, c = idx & 15;
        uint2 hi, lo; split4(vv[u], hi, lo);
        *(uint2*)&Vh[r * 72 + c * 4] = hi;
        *(uint2*)&Vl[r * 72 + c * 4] = lo;
    }
    __syncthreads();

    for (int c0 = 0; c0 < 64; c0++) {
        if (c0 < 63) {
            const int tb = (c0 + 1) * 32;
            #pragma unroll
            for (int u = 0; u < 4; u++) {
                const int idx = u * 256 + tid, r = idx >> 3, c = idx & 7;
                pp[u] = *(const float4*)&gp[((size_t)bh * T_ + q0 + r) * T_ + tb + c * 4];
            }
            #pragma unroll
            for (int u = 0; u < 2; u++) {
                const int idx = u * 256 + tid, r = idx >> 4, c = idx & 15;
                vv[u] = *(const float4*)&gv[((size_t)bh * T_ + tb + r) * DH_ + c * 4];
            }
        }

        #pragma unroll
        for (int ks = 0; ks < 32; ks += 16) {
            FragA ah[2], al[2];
            FragBr bh2[2], bl2[2];
            #pragma unroll
            for (int i = 0; i < 2; i++) {
                wmma::load_matrix_sync(ah[i], &Ph[(wm0 + i * 16) * 40 + ks], 40);
                wmma::load_matrix_sync(al[i], &Pl[(wm0 + i * 16) * 40 + ks], 40);
            }
            #pragma unroll
            for (int j = 0; j < 2; j++) {
                wmma::load_matrix_sync(bh2[j], &Vh[ks * 72 + wn0 + j * 16], 72);
                wmma::load_matrix_sync(bl2[j], &Vl[ks * 72 + wn0 + j * 16], 72);
            }
            #pragma unroll
            for (int i = 0; i < 2; i++)
                #pragma unroll
                for (int j = 0; j < 2; j++) {
                    wmma::mma_sync(acc[i][j], ah[i], bh2[j], acc[i][j]);
                    wmma::mma_sync(acc[i][j], ah[i], bl2[j], acc[i][j]);
                    wmma::mma_sync(acc[i][j], al[i], bh2[j], acc[i][j]);
                }
        }
        __syncthreads();
        if (c0 < 63) {
            #pragma unroll
            for (int u = 0; u < 4; u++) {
                const int idx = u * 256 + tid, r = idx >> 3, c = idx & 7;
                uint2 hi, lo; split4(pp[u], hi, lo);
                *(uint2*)&Ph[r * 40 + c * 4] = hi;
                *(uint2*)&Pl[r * 40 + c * 4] = lo;
            }
            #pragma unroll
            for (int u = 0; u < 2; u++) {
                const int idx = u * 256 + tid, r = idx >> 4, c = idx & 15;
                uint2 hi, lo; split4(vv[u], hi, lo);
                *(uint2*)&Vh[r * 72 + c * 4] = hi;
                *(uint2*)&Vl[r * 72 + c * 4] = lo;
            }
            __syncthreads();
        }
    }

    const int bb = bh >> 3, hh = bh & 7;
    #pragma unroll
    for (int i = 0; i < 2; i++)
        #pragma unroll
        for (int j = 0; j < 2; j++)
            wmma::store_matrix_sync(
                gctx + ((size_t)bb * T_ + q0 + wm0 + i * 16) * DM_ + hh * DH_ + wn0 + j * 16,
                acc[i][j], DM_, wmma::mem_row_major);
}

// ---------------------------------------------------------------------------

extern "C" void kernel_launch(void* const* d_in, const int* in_sizes, int n_in,
                              void* d_out, int out_size)
{
    const float* Q  = (const float*)d_in[0];
    const float* K  = (const float*)d_in[1];
    const float* V  = (const float*)d_in[2];
    const float* Wq = (const float*)d_in[3];
    const float* bq = (const float*)d_in[4];
    const float* Wk = (const float*)d_in[5];
    const float* bk = (const float*)d_in[6];
    const float* Wv = (const float*)d_in[7];
    const float* bv = (const float*)d_in[8];
    const float* Wo = (const float*)d_in[9];
    const float* bo = (const float*)d_in[10];

    float* out  = (float*)d_out;
    float* attn = out + (size_t)M_ * DM_;   // tuple order: (out, attn)

    float *pq, *pk, *pv, *pctx;
    cudaGetSymbolAddress((void**)&pq,   g_q);
    cudaGetSymbolAddress((void**)&pk,   g_k);
    cudaGetSymbolAddress((void**)&pv,   g_v);
    cudaGetSymbolAddress((void**)&pctx, g_ctx);

    cudaFuncSetAttribute(qk_kernel, cudaFuncAttributeMaxDynamicSharedMemorySize, QK_SMEM);

    dim3 pgrid(DM_ / 64, M_ / 128);   // (8, 64)

    gemm_proj<<<pgrid, 256>>>(Q, Wq, bq, pq, 0);
    gemm_proj<<<pgrid, 256>>>(K, Wk, bk, pk, 0);
    gemm_proj<<<pgrid, 256>>>(V, Wv, bv, pv, 0);

    qk_kernel<<<dim3(16, 16, 32), 256, QK_SMEM>>>(pq, pk, attn);
    softmax_kernel<<<BH_ * T_, 256>>>(attn);
    pv_kernel<<<dim3(16, 32), 256>>>(attn, pv, pctx);

    gemm_proj<<<pgrid, 256>>>(pctx, Wo, bo, out, 2);
}